// round 15
// baseline (speedup 1.0000x reference)
#include <cuda_runtime.h>
#include <math.h>
#include <float.h>

// ---------------------------------------------------------------------------
// Render_53412213293435 : triangle rasterizer with z-buffer + UV texture.
//
// Winner per pixel = argmax over (z, face idx)  [z >= zbuf update rule].
// Pipeline:
//   setup_kernel  : per-triangle precompute (exact w, bbox, cheap edge
//                   coeffs, z-plane + guard, UVs) + global min-z.
//   bin_kernel    : one block per 64x64 supertile; conservative bbox+edge
//                   rejection writes surviving triangle indices to a list.
//                   (supertile bounds contain tile bounds with the same
//                   margins, so rejection here is exact-safe for all tiles.)
//   render_kernel : 32x32 tiles, 512 threads, 2 px/thread.  Phase A scans
//                   only the supertile list; tile z floor from covering
//                   triangles; floor-prune; 256-bucket counting sort by
//                   conservative tile-max z; phase B scans sorted candidates
//                   with exact-safe z-plane / guarded-edge rejects; survivors
//                   run the exact reference float32 op order.
// ---------------------------------------------------------------------------

#define MAXTRI 4096
#define MAXBIN 1024
#define TILE_W 32
#define TILE_H 32
#define STILE 64
#define NTHR 512
#define NB 256
#define EPS_E 1e-3f
#define MAXST 64

__device__ float4 g_v0[MAXTRI];     // ax, ay, bx, by
__device__ float4 g_v1[MAXTRI];     // cx, cy, w, z0
__device__ float4 g_wz[MAXTRI];     // w, z0, z1, z2
__device__ float4 g_bbox[MAXTRI];   // minx, miny, maxx, maxy (sentinel if culled)
__device__ float4 g_eAB[MAXTRI];    // ExAB, EyAB, CAB, w
__device__ float4 g_eCB[MAXTRI];    // ExCB, EyCB, CCB, 0
__device__ float4 g_zp[MAXTRI];     // Zx, Zy, Zc+guard, guard
__device__ float4 g_uv01[MAXTRI];   // u0, v0, u1, v1   (already *2-1)
__device__ float2 g_uv2[MAXTRI];    // u2, v2
__device__ unsigned int g_zinit_enc;
__device__ int g_stcnt[MAXST];
__device__ int g_stlist[MAXST][MAXTRI];

// area2d(B, P, A) = (P.x-B.x)*(A.y-B.y) - (P.y-B.y)*(A.x-B.x)  (exact order)
__device__ __forceinline__ float edgef(float px, float py,
                                       float bx, float by,
                                       float ax, float ay) {
    return __fsub_rn(__fmul_rn(__fsub_rn(px, bx), __fsub_rn(ay, by)),
                     __fmul_rn(__fsub_rn(py, by), __fsub_rn(ax, bx)));
}

__device__ __forceinline__ unsigned int fenc(float f) {
    unsigned int u = __float_as_uint(f);
    return (u & 0x80000000u) ? ~u : (u | 0x80000000u);
}
__device__ __forceinline__ float fdec(unsigned int e) {
    return __uint_as_float((e & 0x80000000u) ? (e & 0x7fffffffu) : ~e);
}

// ---------------------------------------------------------------------------
__global__ void setup_kernel(const float* __restrict__ verts,
                             const int*   __restrict__ faces,
                             const float* __restrict__ uv,
                             const int*   __restrict__ uvfaces,
                             int K, int V) {
    int t = blockIdx.x * blockDim.x + threadIdx.x;

    if (t < V)
        atomicMin(&g_zinit_enc, fenc(verts[3 * t + 2]));

    if (t >= K || t >= MAXTRI) return;

    int f0 = faces[3 * t], f1 = faces[3 * t + 1], f2 = faces[3 * t + 2];
    float ax = verts[3 * f0], ay = verts[3 * f0 + 1], z0 = verts[3 * f0 + 2];
    float bx = verts[3 * f1], by = verts[3 * f1 + 1], z1 = verts[3 * f1 + 2];
    float cx = verts[3 * f2], cy = verts[3 * f2 + 1], z2 = verts[3 * f2 + 2];

    // w: same float expression as reference
    float e1x = __fsub_rn(bx, ax), e1y = __fsub_rn(by, ay);
    float e2x = __fsub_rn(cx, ax), e2y = __fsub_rn(cy, ay);
    float w = __fsub_rn(__fmul_rn(e1x, e2y), __fmul_rn(e1y, e2x));

    g_v0[t] = make_float4(ax, ay, bx, by);
    g_v1[t] = make_float4(cx, cy, w, z0);
    g_wz[t] = make_float4(w, z0, z1, z2);

    if (w >= 1e-9f) {
        float mnx = fminf(ax, fminf(bx, cx));
        float mxx = fmaxf(ax, fmaxf(bx, cx));
        float mny = fminf(ay, fminf(by, cy));
        float mxy = fmaxf(ay, fmaxf(by, cy));
        g_bbox[t] = make_float4(mnx, mny, mxx, mxy);
    } else {
        g_bbox[t] = make_float4(2e9f, 2e9f, -2e9f, -2e9f);  // never overlaps
    }

    // cheap edge coefficients (double precision -> float)
    {
        double dax = ax, day = ay, dbx = bx, dby = by, dcx = cx, dcy = cy;
        double ExAB = day - dby, EyAB = dbx - dax;
        double CAB  = dby * (dax - dbx) - dbx * (day - dby);
        double ExCB = dby - dcy, EyCB = dcx - dbx;
        double CCB  = dcy * (dbx - dcx) - dcx * (dby - dcy);
        g_eAB[t] = make_float4((float)ExAB, (float)EyAB, (float)CAB, w);
        g_eCB[t] = make_float4((float)ExCB, (float)EyCB, (float)CCB, 0.f);
    }

    // z-plane + conservative guard
    {
        double dw = (double)(bx - ax) * (double)(cy - ay)
                  - (double)(by - ay) * (double)(cx - ax);
        float4 zp;
        if (w < 1e-4f || dw == 0.0) {
            zp = make_float4(0.f, 0.f, 3.0e37f, 0.f);  // sliver: zub = +huge
        } else {
            double dz1 = (double)z1 - (double)z0;
            double dz2 = (double)z2 - (double)z0;
            double Zx = (dz1 * (double)(cy - ay) - dz2 * (double)(by - ay)) / dw;
            double Zy = (dz2 * (double)(bx - ax) - dz1 * (double)(cx - ax)) / dw;
            double Zc = (double)z0 - Zx * ax - Zy * ay;
            double M = fabs((double)ax);
            M = fmax(M, fabs((double)ay)); M = fmax(M, fabs((double)bx));
            M = fmax(M, fabs((double)by)); M = fmax(M, fabs((double)cx));
            M = fmax(M, fabs((double)cy));
            double Pmax = 4.0 * M * (1.0 + M) + 4.0;   // bound on |edge fn| in tile
            double zmag = fabs((double)z0) + fabs((double)z1) + fabs((double)z2);
            double Zmag = fabs(Zx) + fabs(Zy) + fabs(Zc);
            double guard = 1e-6 * zmag * Pmax / (double)w   // ref w1/w2 rounding
                         + 4e-7 * (Zmag + zmag)             // plane coeff/eval
                         + 1e-5;
            zp = make_float4((float)Zx, (float)Zy, (float)(Zc + guard),
                             (float)guard);
        }
        g_zp[t] = zp;
    }

    int m0 = uvfaces[3 * t], m1 = uvfaces[3 * t + 1], m2 = uvfaces[3 * t + 2];
    float u0 = __fsub_rn(__fmul_rn(uv[2 * m0], 2.0f), 1.0f);
    float v0 = __fsub_rn(__fmul_rn(uv[2 * m0 + 1], 2.0f), 1.0f);
    float u1 = __fsub_rn(__fmul_rn(uv[2 * m1], 2.0f), 1.0f);
    float v1 = __fsub_rn(__fmul_rn(uv[2 * m1 + 1], 2.0f), 1.0f);
    float u2 = __fsub_rn(__fmul_rn(uv[2 * m2], 2.0f), 1.0f);
    float v2 = __fsub_rn(__fmul_rn(uv[2 * m2 + 1], 2.0f), 1.0f);
    g_uv01[t] = make_float4(u0, v0, u1, v1);
    g_uv2[t]  = make_float2(u2, v2);
}

// ---------------------------------------------------------------------------
// bin_kernel: one block per 64x64 supertile; conservative reject vs the
// supertile (same margins as the tile tests -> exact-safe superset).
__global__ void bin_kernel(int K, int S, int nstx) {
    const int st = blockIdx.x;
    const int sx = st % nstx, sy = st / nstx;
    const float step = __fdiv_rn(2.0f, (float)(S - 1));

    const int jA = sx * STILE, jB = min(jA + STILE - 1, S - 1);
    const int iA = sy * STILE, iB = min(iA + STILE - 1, S - 1);
    const float MARGIN = 1e-4f;
    const float txLo = -1.0f + (float)jA * step - MARGIN;
    const float txHi = -1.0f + (float)jB * step + MARGIN;
    const float tyLo = -1.0f + (float)(S - 1 - iB) * step - MARGIN;
    const float tyHi = -1.0f + (float)(S - 1 - iA) * step + MARGIN;

    for (int t = threadIdx.x; t < K; t += blockDim.x) {
        float4 bb = g_bbox[t];
        if (bb.z < txLo || bb.x > txHi || bb.w < tyLo || bb.y > tyHi) continue;

        float4 v0 = g_v0[t];
        float4 v1 = g_v1[t];
        float ax = v0.x, ay = v0.y, bx = v0.z, by = v0.w;
        float cx = v1.x, cy = v1.y;
        {
            float ex = ((ay - by) > 0.f) ? txHi : txLo;
            float ey = ((ax - bx) < 0.f) ? tyHi : tyLo;
            if (edgef(ex, ey, bx, by, ax, ay) <= -1e-6f) continue;
        }
        {
            float ex = ((by - cy) > 0.f) ? txHi : txLo;
            float ey = ((bx - cx) < 0.f) ? tyHi : tyLo;
            if (edgef(ex, ey, cx, cy, bx, by) <= -1e-6f) continue;
        }
        {
            float ex = ((cy - ay) > 0.f) ? txHi : txLo;
            float ey = ((cx - ax) < 0.f) ? tyHi : tyLo;
            if (edgef(ex, ey, ax, ay, cx, cy) <= -1e-6f) continue;
        }
        int slot = atomicAdd(&g_stcnt[st], 1);
        if (slot < MAXTRI) g_stlist[st][slot] = t;
    }
}

// ---------------------------------------------------------------------------
#define CPT 4   // max candidates per thread in phase A (ceil(2048/512))

// texture sample + store for one pixel
__device__ __forceinline__ void shade_pixel(
    const float* __restrict__ uvmap, float* __restrict__ out,
    int besti, float bw1, float bw2, int i, int j, int S, int T) {
    const size_t plane = (size_t)S * S;
    const size_t pix = (size_t)i * S + j;

    float r = 0.f, g = 0.f, b = 0.f, a = 0.f;
    if (besti >= 0) {
        float4 uv01 = g_uv01[besti];
        float2 uv2  = g_uv2[besti];
        float w3 = __fsub_rn(__fsub_rn(1.0f, bw1), bw2);
        float u = __fadd_rn(__fadd_rn(__fmul_rn(bw1, uv01.x),
                                      __fmul_rn(bw2, uv01.z)),
                            __fmul_rn(w3, uv2.x));
        float v = __fadd_rn(__fadd_rn(__fmul_rn(bw1, uv01.y),
                                      __fmul_rn(bw2, uv01.w)),
                            __fmul_rn(w3, uv2.y));

        const float Wm1 = (float)(T - 1);
        float ix = __fmul_rn(__fmul_rn(__fadd_rn(u, 1.0f), Wm1), 0.5f);
        float iy = __fmul_rn(__fmul_rn(__fadd_rn(v, 1.0f), Wm1), 0.5f);
        float ix0 = floorf(ix), iy0 = floorf(iy);
        float ix1 = __fadd_rn(ix0, 1.0f), iy1 = __fadd_rn(iy0, 1.0f);
        float wx1 = __fsub_rn(ix, ix0), wx0 = __fsub_rn(1.0f, wx1);
        float wy1 = __fsub_rn(iy, iy0), wy0 = __fsub_rn(1.0f, wy1);

        float inx0 = (ix0 >= 0.f && ix0 <= Wm1) ? 1.f : 0.f;
        float inx1 = (ix1 >= 0.f && ix1 <= Wm1) ? 1.f : 0.f;
        float iny0 = (iy0 >= 0.f && iy0 <= Wm1) ? 1.f : 0.f;
        float iny1 = (iy1 >= 0.f && iy1 <= Wm1) ? 1.f : 0.f;
        float f00 = __fmul_rn(iny0, inx0), f01 = __fmul_rn(iny0, inx1);
        float f10 = __fmul_rn(iny1, inx0), f11 = __fmul_rn(iny1, inx1);

        int jx0 = (int)fminf(fmaxf(ix0, 0.f), Wm1);
        int jx1 = (int)fminf(fmaxf(ix1, 0.f), Wm1);
        int jy0 = (int)fminf(fmaxf(iy0, 0.f), Wm1);
        int jy1 = (int)fminf(fmaxf(iy1, 0.f), Wm1);

        float W00 = __fmul_rn(wy0, wx0), W01 = __fmul_rn(wy0, wx1);
        float W10 = __fmul_rn(wy1, wx0), W11 = __fmul_rn(wy1, wx1);

        const size_t tplane = (size_t)T * T;
        const size_t o00 = (size_t)jy0 * T + jx0;
        const size_t o01 = (size_t)jy0 * T + jx1;
        const size_t o10 = (size_t)jy1 * T + jx0;
        const size_t o11 = (size_t)jy1 * T + jx1;

        float rgb[3];
#pragma unroll
        for (int c = 0; c < 3; c++) {
            const float* pl = uvmap + c * tplane;
            float t00 = __fmul_rn(__ldg(pl + o00), f00);
            float t01 = __fmul_rn(__ldg(pl + o01), f01);
            float t10 = __fmul_rn(__ldg(pl + o10), f10);
            float t11 = __fmul_rn(__ldg(pl + o11), f11);
            rgb[c] = __fadd_rn(__fadd_rn(__fadd_rn(__fmul_rn(t00, W00),
                                                   __fmul_rn(t01, W01)),
                                         __fmul_rn(t10, W10)),
                               __fmul_rn(t11, W11));
        }
        r = rgb[0]; g = rgb[1]; b = rgb[2]; a = 1.0f;
    }
    out[pix]             = r;
    out[plane + pix]     = g;
    out[2 * plane + pix] = b;
    out[3 * plane + pix] = a;
}

__global__ __launch_bounds__(NTHR, 2)
void render_kernel(const float* __restrict__ uvmap,
                   float* __restrict__ out,
                   int K, int S, int T, int nstx) {
    // dynamic smem: [s_e0 | s_e1 | s_e2], MAXBIN float4 each
    extern __shared__ float4 s_dyn[];
    float4* s_e0 = s_dyn;                 // ExAB, EyAB, CAB, w
    float4* s_e1 = s_dyn + MAXBIN;        // ExCB, EyCB, CCB, idx_bits
    float4* s_e2 = s_dyn + 2 * MAXBIN;    // Zx, Zy, Zcg, key_bits

    const float step = __fdiv_rn(2.0f, (float)(S - 1));

    const int jt = blockIdx.x, it = blockIdx.y;
    const int st = (it >> 1) * nstx + (jt >> 1);   // 64x64 supertile id
    const int lj = threadIdx.x & 31;       // 0..31 (column)
    const int li = threadIdx.x >> 5;       // 0..15 (row pair)
    const int jp  = jt * TILE_W + lj;
    const int i0p = it * TILE_H + li;
    const int i1p = i0p + 16;
    const int tid = threadIdx.x;
    const int lane = tid & 31, wid = tid >> 5;

    const float px  = __fadd_rn(-1.0f, __fmul_rn((float)jp, step));
    const float py0 = __fadd_rn(-1.0f, __fmul_rn((float)(S - 1 - i0p), step));
    const float py1 = __fadd_rn(-1.0f, __fmul_rn((float)(S - 1 - i1p), step));

    const int jA = jt * TILE_W, jB = min(jA + TILE_W - 1, S - 1);
    const int iA = it * TILE_H, iB = min(iA + TILE_H - 1, S - 1);
    const float MARGIN = 1e-4f;
    const float txLo = -1.0f + (float)jA * step - MARGIN;
    const float txHi = -1.0f + (float)jB * step + MARGIN;
    const float tyLo = -1.0f + (float)(S - 1 - iB) * step - MARGIN;
    const float tyHi = -1.0f + (float)(S - 1 - iA) * step + MARGIN;

    __shared__ unsigned int s_encmin, s_encmax, s_floor_enc;
    __shared__ int s_total;
    __shared__ int s_hist[NB];
    __shared__ int s_wsum[8];
    if (tid == 0) {
        s_encmin = 0xffffffffu; s_encmax = 0u; s_floor_enc = 0u;
    }
    if (tid < NB) s_hist[tid] = 0;
    __syncthreads();

    // ---- Phase A: scan supertile list; candidates held in registers ----
    const int stn = min(g_stcnt[st], MAXTRI);
    const int* stlist = g_stlist[st];

    float cz[CPT];
    int   ct[CPT];
    int   nc = 0;
#pragma unroll
    for (int itr = 0; itr < CPT; itr++) {
        int idx = tid + itr * NTHR;
        if (idx >= stn) break;
        int t = stlist[idx];
        float4 bb = g_bbox[t];
        if (bb.z < txLo || bb.x > txHi || bb.w < tyLo || bb.y > tyHi) continue;

        float4 v0 = g_v0[t];
        float4 v1 = g_v1[t];
        float ax = v0.x, ay = v0.y, bx = v0.z, by = v0.w;
        float cx = v1.x, cy = v1.y, w = v1.z;

        // per-edge eval at max corner (reject) and min corner (coverage)
        float eABmin, eCBmin, eCAmin;
        {
            float gx = (ay - by), gy = -(ax - bx);
            float exM = (gx > 0.f) ? txHi : txLo, eyM = (gy > 0.f) ? tyHi : tyLo;
            if (edgef(exM, eyM, bx, by, ax, ay) <= -1e-6f) continue;
            float exm = (gx > 0.f) ? txLo : txHi, eym = (gy > 0.f) ? tyLo : tyHi;
            eABmin = edgef(exm, eym, bx, by, ax, ay);
        }
        {
            float gx = (by - cy), gy = -(bx - cx);
            float exM = (gx > 0.f) ? txHi : txLo, eyM = (gy > 0.f) ? tyHi : tyLo;
            if (edgef(exM, eyM, cx, cy, bx, by) <= -1e-6f) continue;
            float exm = (gx > 0.f) ? txLo : txHi, eym = (gy > 0.f) ? tyLo : tyHi;
            eCBmin = edgef(exm, eym, cx, cy, bx, by);
        }
        {
            float gx = (cy - ay), gy = -(cx - ax);
            float exM = (gx > 0.f) ? txHi : txLo, eyM = (gy > 0.f) ? tyHi : tyLo;
            if (edgef(exM, eyM, ax, ay, cx, cy) <= -1e-6f) continue;
            float exm = (gx > 0.f) ? txLo : txHi, eym = (gy > 0.f) ? tyLo : tyHi;
            eCAmin = edgef(exm, eym, ax, ay, cx, cy);
        }

        // tile-max z upper bound from z-plane (guard folded into Zcg)
        float zb;
        float4 zp = g_zp[t];
        if (w < 1e-4f) {
            zb = FLT_MAX;
        } else {
            float mx = (zp.x > 0.f) ? txHi : txLo;
            float my = (zp.y > 0.f) ? tyHi : tyLo;
            zb = zp.x * mx + zp.y * my + zp.z;

            // coverage: exact inside at every tile pixel guaranteed when all
            // edge functions clear +1e-3 at their min corners
            if (eABmin > 1e-3f && eCBmin > 1e-3f && eCAmin > 1e-3f) {
                float mx2 = (zp.x > 0.f) ? txLo : txHi;
                float my2 = (zp.y > 0.f) ? tyLo : tyHi;
                float zlo = zp.x * mx2 + zp.y * my2 + (zp.z - 3.0f * zp.w);
                atomicMax(&s_floor_enc, fenc(zlo));
            }
        }
        cz[nc] = zb;
        ct[nc] = t;
        nc++;
    }
    __syncthreads();

    // ---- floor prune BEFORE sort (exact-safe) ----
    const unsigned int floor_enc = max(g_zinit_enc, s_floor_enc);
    {
        int m = 0;
#pragma unroll
        for (int k = 0; k < CPT; k++) {
            if (k >= nc) break;
            unsigned int e = fenc(cz[k]);
            if (e >= floor_enc) {
                cz[m] = cz[k];
                ct[m] = ct[k];
                m++;
                if (cz[k] < FLT_MAX) {
                    atomicMin(&s_encmin, e);
                    atomicMax(&s_encmax, e);
                }
            }
        }
        nc = m;
    }
    __syncthreads();

    // ---- counting sort over survivors (descending z-bound, NB buckets) ----
    float zmin, rangeInv, bw;
    {
        unsigned int emin = s_encmin, emax = s_encmax;
        float fzmin, fzmax;
        if (emin > emax) { fzmin = 0.f; fzmax = 1.f; }
        else { fzmin = fdec(emin); fzmax = fdec(emax); }
        if (!(fzmax > fzmin)) fzmax = fzmin + 1.0f;
        zmin = fzmin;
        bw = (fzmax - fzmin) / (float)NB;
        rangeInv = (float)NB / (fzmax - fzmin);
    }

    int cb[CPT];
#pragma unroll
    for (int k = 0; k < CPT; k++) {
        if (k >= nc) break;
        float zb = cz[k];
        int ib = (zb >= FLT_MAX) ? (NB - 1)
                                 : min(NB - 1, max(0, (int)((zb - zmin) * rangeInv)));
        cb[k] = ib;
        atomicAdd(&s_hist[NB - 1 - ib], 1);
    }
    __syncthreads();

    // exclusive prefix sum over NB=256 buckets (first 8 warps only)
    if (tid < NB) {
        int h = s_hist[tid];
        int v = h;
#pragma unroll
        for (int o = 1; o < 32; o <<= 1) {
            int u = __shfl_up_sync(0xffffffffu, v, o);
            if (lane >= o) v += u;
        }
        if (lane == 31) s_wsum[wid] = v;
        __syncthreads();
        if (tid == 0) {
            int acc = 0;
#pragma unroll
            for (int k = 0; k < 8; k++) { int t2 = s_wsum[k]; s_wsum[k] = acc; acc += t2; }
            s_total = acc;
        }
        __syncthreads();
        s_hist[tid] = v - h + s_wsum[wid];
    } else {
        __syncthreads();
        __syncthreads();
    }
    __syncthreads();
    const int n = min(s_total, MAXBIN);

    // scatter survivors in (approximately) descending-bound order
#pragma unroll
    for (int k = 0; k < CPT; k++) {
        if (k >= nc) break;
        int ib = cb[k];
        int t = ct[k];
        float keyz = (cz[k] >= FLT_MAX) ? FLT_MAX
                                        : zmin + (float)(ib + 2) * bw;  // ub + slack
        int pos = atomicAdd(&s_hist[NB - 1 - ib], 1);
        if (pos < MAXBIN) {
            float4 eab = g_eAB[t];
            float4 ecb = g_eCB[t];
            float4 zp  = g_zp[t];
            s_e0[pos] = eab;                                   // w in .w
            s_e1[pos] = make_float4(ecb.x, ecb.y, ecb.z,
                                    __uint_as_float((unsigned int)t));
            s_e2[pos] = make_float4(zp.x, zp.y, zp.z,
                                    __uint_as_float(fenc(keyz)));
        }
    }
    __syncthreads();

    // ---- Phase B: two pixels per thread (same column), shared loads ----
    unsigned int be0 = floor_enc, be1 = floor_enc;
    float bz0 = fdec(floor_enc), bz1 = bz0;
    int   bi0 = -1, bi1 = -1;
    float w1p0 = 0.f, w2p0 = 0.f, w1p1 = 0.f, w2p1 = 0.f;

    for (int k = 0; k < n; k++) {
        float4 e2 = s_e2[k];
        unsigned int key = __float_as_uint(e2.w);
        bool a0 = (key >= be0);
        bool a1 = (key >= be1);
        if (!a0 && !a1) break;                 // sorted-bound break (both done)

        // zub = Zx*px + Zy*py + Zcg; share the px term
        float zx = e2.x * px;
        float zub0 = zx + fmaf(e2.y, py0, e2.z);
        float zub1 = zx + fmaf(e2.y, py1, e2.z);
        bool c0 = a0 && (zub0 >= bz0);
        bool c1 = a1 && (zub1 >= bz1);
        if (!c0 && !c1) continue;

        float4 e0 = s_e0[k];
        float4 e1 = s_e1[k];
        float ax_ = e0.x * px, bx_ = e1.x * px;
        float pab0 = ax_ + fmaf(e0.y, py0, e0.z);
        float pcb0 = bx_ + fmaf(e1.y, py0, e1.z);
        float pca0 = (e0.w - pab0) - pcb0;
        float pab1 = ax_ + fmaf(e0.y, py1, e0.z);
        float pcb1 = bx_ + fmaf(e1.y, py1, e1.z);
        float pca1 = (e0.w - pab1) - pcb1;
        bool q0 = c0 && pab0 > -EPS_E && pcb0 > -EPS_E && pca0 > -EPS_E;
        bool q1 = c1 && pab1 > -EPS_E && pcb1 > -EPS_E && pca1 > -EPS_E;
        if (!q0 && !q1) continue;

        int t = (int)__float_as_uint(e1.w);
        float4 v0 = g_v0[t];
        float4 v1 = g_v1[t];
        float4 wz = g_wz[t];

        if (q0) {
            float pAB = edgef(px, py0, v0.z, v0.w, v0.x, v0.y);
            float pCB = edgef(px, py0, v1.x, v1.y, v0.z, v0.w);
            float pCA = edgef(px, py0, v0.x, v0.y, v1.x, v1.y);
            if (pAB > 0.f && pCB > 0.f && pCA > 0.f) {
                float w1 = __fdiv_rn(pCB, wz.x);
                float w2 = __fdiv_rn(pCA, wz.x);
                float w3 = __fsub_rn(__fsub_rn(1.0f, w1), w2);
                float z = __fadd_rn(__fadd_rn(__fmul_rn(w1, wz.y),
                                              __fmul_rn(w2, wz.z)),
                                    __fmul_rn(w3, wz.w));
                if (z > bz0 || (z == bz0 && t > bi0)) {
                    bz0 = z; be0 = fenc(z); bi0 = t; w1p0 = w1; w2p0 = w2;
                }
            }
        }
        if (q1) {
            float pAB = edgef(px, py1, v0.z, v0.w, v0.x, v0.y);
            float pCB = edgef(px, py1, v1.x, v1.y, v0.z, v0.w);
            float pCA = edgef(px, py1, v0.x, v0.y, v1.x, v1.y);
            if (pAB > 0.f && pCB > 0.f && pCA > 0.f) {
                float w1 = __fdiv_rn(pCB, wz.x);
                float w2 = __fdiv_rn(pCA, wz.x);
                float w3 = __fsub_rn(__fsub_rn(1.0f, w1), w2);
                float z = __fadd_rn(__fadd_rn(__fmul_rn(w1, wz.y),
                                              __fmul_rn(w2, wz.z)),
                                    __fmul_rn(w3, wz.w));
                if (z > bz1 || (z == bz1 && t > bi1)) {
                    bz1 = z; be1 = fenc(z); bi1 = t; w1p1 = w1; w2p1 = w2;
                }
            }
        }
    }

    if (jp < S) {
        if (i0p < S) shade_pixel(uvmap, out, bi0, w1p0, w2p0, i0p, jp, S, T);
        if (i1p < S) shade_pixel(uvmap, out, bi1, w1p1, w2p1, i1p, jp, S, T);
    }
}

// ---------------------------------------------------------------------------
extern "C" void kernel_launch(void* const* d_in, const int* in_sizes, int n_in,
                              void* d_out, int out_size) {
    const float* vertices = (const float*)d_in[0];
    const int*   faces    = (const int*)  d_in[1];
    const float* uv       = (const float*)d_in[2];
    const int*   uvfaces  = (const int*)  d_in[3];
    const float* uvmap    = (const float*)d_in[4];

    int V = in_sizes[0] / 3;
    int K = in_sizes[1] / 3;
    int T = (int)(sqrt((double)in_sizes[4] / 3.0) + 0.5);
    int S = (int)(sqrt((double)out_size / 4.0) + 0.5);
    int Keff = (K < MAXTRI) ? K : MAXTRI;

    int nstx = (S + STILE - 1) / STILE;
    int nsty = (S + STILE - 1) / STILE;
    int nst = nstx * nsty;   // 64 for S=512

    void* zinit_addr = nullptr;
    cudaGetSymbolAddress(&zinit_addr, g_zinit_enc);
    cudaMemsetAsync(zinit_addr, 0xFF, sizeof(unsigned int), 0);
    void* stcnt_addr = nullptr;
    cudaGetSymbolAddress(&stcnt_addr, g_stcnt);
    cudaMemsetAsync(stcnt_addr, 0, sizeof(int) * MAXST, 0);

    int KV = (K > V) ? K : V;
    setup_kernel<<<(KV + 255) / 256, 256>>>(vertices, faces, uv, uvfaces,
                                            Keff, V);
    bin_kernel<<<nst, 256>>>(Keff, S, nstx);

    const int DYN = 3 * MAXBIN * sizeof(float4);   // 49152 bytes
    static int attr_done = 0;
    if (!attr_done) {
        cudaFuncSetAttribute(render_kernel,
                             cudaFuncAttributeMaxDynamicSharedMemorySize, DYN);
        attr_done = 1;
    }

    dim3 grid((S + TILE_W - 1) / TILE_W, (S + TILE_H - 1) / TILE_H);
    render_kernel<<<grid, NTHR, DYN>>>(uvmap, (float*)d_out,
                                       Keff, S, T, nstx);
}

// round 16
// speedup vs baseline: 1.3316x; 1.3316x over previous
#include <cuda_runtime.h>
#include <math.h>
#include <float.h>

// ---------------------------------------------------------------------------
// Render_53412213293435 : triangle rasterizer with z-buffer + UV texture.
//
// Winner per pixel = argmax over (z, face idx)  [z >= zbuf update rule].
// 32x32-pixel tiles, 512 threads, TWO pixels per thread (rows i, i+16);
// 256 blocks, single wave.  Phase A bins + tile z floor; floor-prune before
// a 256-bucket counting sort; phase B scans sorted candidates with exact-
// safe z-plane / guarded-edge rejects; survivors run the exact reference
// float32 op order.  Setup is all-FP32: the z-plane guard is inflated with
// conservative bounds on the float-precision coefficient errors.
// ---------------------------------------------------------------------------

#define MAXTRI 4096
#define MAXBIN 1024
#define TILE_W 32
#define TILE_H 32
#define NTHR 512
#define NB 256
#define EPS_E 1e-3f

__device__ float4 g_v0[MAXTRI];     // ax, ay, bx, by
__device__ float4 g_v1[MAXTRI];     // cx, cy, w, z0
__device__ float4 g_wz[MAXTRI];     // w, z0, z1, z2
__device__ float4 g_bbox[MAXTRI];   // minx, miny, maxx, maxy (sentinel if culled)
__device__ float4 g_eAB[MAXTRI];    // ExAB, EyAB, CAB, w
__device__ float4 g_eCB[MAXTRI];    // ExCB, EyCB, CCB, 0
__device__ float4 g_zp[MAXTRI];     // Zx, Zy, Zc+guard, guard
__device__ float4 g_uv01[MAXTRI];   // u0, v0, u1, v1   (already *2-1)
__device__ float2 g_uv2[MAXTRI];    // u2, v2
__device__ unsigned int g_zinit_enc;

// area2d(B, P, A) = (P.x-B.x)*(A.y-B.y) - (P.y-B.y)*(A.x-B.x)  (exact order)
__device__ __forceinline__ float edgef(float px, float py,
                                       float bx, float by,
                                       float ax, float ay) {
    return __fsub_rn(__fmul_rn(__fsub_rn(px, bx), __fsub_rn(ay, by)),
                     __fmul_rn(__fsub_rn(py, by), __fsub_rn(ax, bx)));
}

__device__ __forceinline__ unsigned int fenc(float f) {
    unsigned int u = __float_as_uint(f);
    return (u & 0x80000000u) ? ~u : (u | 0x80000000u);
}
__device__ __forceinline__ float fdec(unsigned int e) {
    return __uint_as_float((e & 0x80000000u) ? (e & 0x7fffffffu) : ~e);
}

// ---------------------------------------------------------------------------
__global__ void setup_kernel(const float* __restrict__ verts,
                             const int*   __restrict__ faces,
                             const float* __restrict__ uv,
                             const int*   __restrict__ uvfaces,
                             int K, int V) {
    int t = blockIdx.x * blockDim.x + threadIdx.x;

    if (t < V)
        atomicMin(&g_zinit_enc, fenc(verts[3 * t + 2]));

    if (t >= K || t >= MAXTRI) return;

    int f0 = faces[3 * t], f1 = faces[3 * t + 1], f2 = faces[3 * t + 2];
    float ax = verts[3 * f0], ay = verts[3 * f0 + 1], z0 = verts[3 * f0 + 2];
    float bx = verts[3 * f1], by = verts[3 * f1 + 1], z1 = verts[3 * f1 + 2];
    float cx = verts[3 * f2], cy = verts[3 * f2 + 1], z2 = verts[3 * f2 + 2];

    // w: same float expression as reference
    float e1x = __fsub_rn(bx, ax), e1y = __fsub_rn(by, ay);
    float e2x = __fsub_rn(cx, ax), e2y = __fsub_rn(cy, ay);
    float w = __fsub_rn(__fmul_rn(e1x, e2y), __fmul_rn(e1y, e2x));

    g_v0[t] = make_float4(ax, ay, bx, by);
    g_v1[t] = make_float4(cx, cy, w, z0);
    g_wz[t] = make_float4(w, z0, z1, z2);

    if (w >= 1e-9f) {
        float mnx = fminf(ax, fminf(bx, cx));
        float mxx = fmaxf(ax, fmaxf(bx, cx));
        float mny = fminf(ay, fminf(by, cy));
        float mxy = fmaxf(ay, fmaxf(by, cy));
        g_bbox[t] = make_float4(mnx, mny, mxx, mxy);
    } else {
        g_bbox[t] = make_float4(2e9f, 2e9f, -2e9f, -2e9f);  // never overlaps
    }

    // cheap edge coefficients (float; edge pre-test guard band 1e-3 >> err)
    {
        float ExAB = ay - by, EyAB = bx - ax;
        float CAB  = by * (ax - bx) - bx * (ay - by);
        float ExCB = by - cy, EyCB = cx - bx;
        float CCB  = cy * (bx - cx) - cx * (by - cy);
        g_eAB[t] = make_float4(ExAB, EyAB, CAB, w);
        g_eCB[t] = make_float4(ExCB, EyCB, CCB, 0.f);
    }

    // z-plane + conservative guard (all float; guard inflated for the
    // float-precision coefficient errors -- see error analysis below)
    {
        float4 zp;
        if (w < 1e-4f) {
            zp = make_float4(0.f, 0.f, 3.0e37f, 0.f);  // sliver: zub = +huge
        } else {
            float dz1 = z1 - z0;
            float dz2 = z2 - z0;
            float Zx = (dz1 * (cy - ay) - dz2 * (by - ay)) / w;
            float Zy = (dz2 * (bx - ax) - dz1 * (cx - ax)) / w;
            float Zc = z0 - Zx * ax - Zy * ay;

            float M = fabsf(ax);
            M = fmaxf(M, fabsf(ay)); M = fmaxf(M, fabsf(bx));
            M = fmaxf(M, fabsf(by)); M = fmaxf(M, fabsf(cx));
            M = fmaxf(M, fabsf(cy));
            float Pmax = 4.0f * M * (1.0f + M) + 4.0f;  // bound on |edge fn|
            float zmag = fabsf(z0) + fabsf(z1) + fabsf(z2);
            float Zmag = fabsf(Zx) + fabsf(Zy) + fabsf(Zc);

            // float-computation error bounds (conservative, x2 safety):
            //   err(w)   <= 4e-7 * M^2          -> relw = err(w)/w
            //   |num|    <= 4 * zmag * M
            //   err(Zxy) <= (5e-7*|num| + |num|*relw) / w
            //   err(Zc)  <= 5e-7*zmag + 2*M*err(Zxy)
            float relw = (4e-7f * M * M) / w;
            float numM = 4.0f * zmag * M;
            float errZ = (numM * 5e-7f + numM * relw) / w;
            float errZc = 5e-7f * zmag + 2.0f * M * errZ;
            float coefErr = 2.0f * (2.0f * errZ + errZc);

            float guard = 1e-6f * zmag * Pmax / w   // reference w1/w2 rounding
                        + coefErr                    // float coefficient error
                        + 4e-7f * (Zmag + zmag)      // evaluation rounding
                        + 1e-5f;
            zp = make_float4(Zx, Zy, Zc + guard, guard);
        }
        g_zp[t] = zp;
    }

    int m0 = uvfaces[3 * t], m1 = uvfaces[3 * t + 1], m2 = uvfaces[3 * t + 2];
    float u0 = __fsub_rn(__fmul_rn(uv[2 * m0], 2.0f), 1.0f);
    float v0 = __fsub_rn(__fmul_rn(uv[2 * m0 + 1], 2.0f), 1.0f);
    float u1 = __fsub_rn(__fmul_rn(uv[2 * m1], 2.0f), 1.0f);
    float v1 = __fsub_rn(__fmul_rn(uv[2 * m1 + 1], 2.0f), 1.0f);
    float u2 = __fsub_rn(__fmul_rn(uv[2 * m2], 2.0f), 1.0f);
    float v2 = __fsub_rn(__fmul_rn(uv[2 * m2 + 1], 2.0f), 1.0f);
    g_uv01[t] = make_float4(u0, v0, u1, v1);
    g_uv2[t]  = make_float2(u2, v2);
}

// ---------------------------------------------------------------------------
#define CPT 4   // max candidates per thread in phase A (ceil(2048/512))

// texture sample + store for one pixel
__device__ __forceinline__ void shade_pixel(
    const float* __restrict__ uvmap, float* __restrict__ out,
    int besti, float bw1, float bw2, int i, int j, int S, int T) {
    const size_t plane = (size_t)S * S;
    const size_t pix = (size_t)i * S + j;

    float r = 0.f, g = 0.f, b = 0.f, a = 0.f;
    if (besti >= 0) {
        float4 uv01 = g_uv01[besti];
        float2 uv2  = g_uv2[besti];
        float w3 = __fsub_rn(__fsub_rn(1.0f, bw1), bw2);
        float u = __fadd_rn(__fadd_rn(__fmul_rn(bw1, uv01.x),
                                      __fmul_rn(bw2, uv01.z)),
                            __fmul_rn(w3, uv2.x));
        float v = __fadd_rn(__fadd_rn(__fmul_rn(bw1, uv01.y),
                                      __fmul_rn(bw2, uv01.w)),
                            __fmul_rn(w3, uv2.y));

        const float Wm1 = (float)(T - 1);
        float ix = __fmul_rn(__fmul_rn(__fadd_rn(u, 1.0f), Wm1), 0.5f);
        float iy = __fmul_rn(__fmul_rn(__fadd_rn(v, 1.0f), Wm1), 0.5f);
        float ix0 = floorf(ix), iy0 = floorf(iy);
        float ix1 = __fadd_rn(ix0, 1.0f), iy1 = __fadd_rn(iy0, 1.0f);
        float wx1 = __fsub_rn(ix, ix0), wx0 = __fsub_rn(1.0f, wx1);
        float wy1 = __fsub_rn(iy, iy0), wy0 = __fsub_rn(1.0f, wy1);

        float inx0 = (ix0 >= 0.f && ix0 <= Wm1) ? 1.f : 0.f;
        float inx1 = (ix1 >= 0.f && ix1 <= Wm1) ? 1.f : 0.f;
        float iny0 = (iy0 >= 0.f && iy0 <= Wm1) ? 1.f : 0.f;
        float iny1 = (iy1 >= 0.f && iy1 <= Wm1) ? 1.f : 0.f;
        float f00 = __fmul_rn(iny0, inx0), f01 = __fmul_rn(iny0, inx1);
        float f10 = __fmul_rn(iny1, inx0), f11 = __fmul_rn(iny1, inx1);

        int jx0 = (int)fminf(fmaxf(ix0, 0.f), Wm1);
        int jx1 = (int)fminf(fmaxf(ix1, 0.f), Wm1);
        int jy0 = (int)fminf(fmaxf(iy0, 0.f), Wm1);
        int jy1 = (int)fminf(fmaxf(iy1, 0.f), Wm1);

        float W00 = __fmul_rn(wy0, wx0), W01 = __fmul_rn(wy0, wx1);
        float W10 = __fmul_rn(wy1, wx0), W11 = __fmul_rn(wy1, wx1);

        const size_t tplane = (size_t)T * T;
        const size_t o00 = (size_t)jy0 * T + jx0;
        const size_t o01 = (size_t)jy0 * T + jx1;
        const size_t o10 = (size_t)jy1 * T + jx0;
        const size_t o11 = (size_t)jy1 * T + jx1;

        float rgb[3];
#pragma unroll
        for (int c = 0; c < 3; c++) {
            const float* pl = uvmap + c * tplane;
            float t00 = __fmul_rn(__ldg(pl + o00), f00);
            float t01 = __fmul_rn(__ldg(pl + o01), f01);
            float t10 = __fmul_rn(__ldg(pl + o10), f10);
            float t11 = __fmul_rn(__ldg(pl + o11), f11);
            rgb[c] = __fadd_rn(__fadd_rn(__fadd_rn(__fmul_rn(t00, W00),
                                                   __fmul_rn(t01, W01)),
                                         __fmul_rn(t10, W10)),
                               __fmul_rn(t11, W11));
        }
        r = rgb[0]; g = rgb[1]; b = rgb[2]; a = 1.0f;
    }
    out[pix]             = r;
    out[plane + pix]     = g;
    out[2 * plane + pix] = b;
    out[3 * plane + pix] = a;
}

__global__ __launch_bounds__(NTHR, 2)
void render_kernel(const float* __restrict__ uvmap,
                   float* __restrict__ out,
                   int K, int S, int T) {
    // dynamic smem: [s_e0 | s_e1 | s_e2], MAXBIN float4 each
    extern __shared__ float4 s_dyn[];
    float4* s_e0 = s_dyn;                 // ExAB, EyAB, CAB, w
    float4* s_e1 = s_dyn + MAXBIN;        // ExCB, EyCB, CCB, idx_bits
    float4* s_e2 = s_dyn + 2 * MAXBIN;    // Zx, Zy, Zcg, key_bits

    const float step = __fdiv_rn(2.0f, (float)(S - 1));

    const int jt = blockIdx.x, it = blockIdx.y;
    const int lj = threadIdx.x & 31;       // 0..31 (column)
    const int li = threadIdx.x >> 5;       // 0..15 (row pair)
    const int jp  = jt * TILE_W + lj;
    const int i0p = it * TILE_H + li;
    const int i1p = i0p + 16;
    const int tid = threadIdx.x;
    const int lane = tid & 31, wid = tid >> 5;

    const float px  = __fadd_rn(-1.0f, __fmul_rn((float)jp, step));
    const float py0 = __fadd_rn(-1.0f, __fmul_rn((float)(S - 1 - i0p), step));
    const float py1 = __fadd_rn(-1.0f, __fmul_rn((float)(S - 1 - i1p), step));

    const int jA = jt * TILE_W, jB = min(jA + TILE_W - 1, S - 1);
    const int iA = it * TILE_H, iB = min(iA + TILE_H - 1, S - 1);
    const float MARGIN = 1e-4f;
    const float txLo = -1.0f + (float)jA * step - MARGIN;
    const float txHi = -1.0f + (float)jB * step + MARGIN;
    const float tyLo = -1.0f + (float)(S - 1 - iB) * step - MARGIN;
    const float tyHi = -1.0f + (float)(S - 1 - iA) * step + MARGIN;

    __shared__ unsigned int s_encmin, s_encmax, s_floor_enc;
    __shared__ int s_total;
    __shared__ int s_hist[NB];
    __shared__ int s_wsum[8];
    if (tid == 0) {
        s_encmin = 0xffffffffu; s_encmax = 0u; s_floor_enc = 0u;
    }
    if (tid < NB) s_hist[tid] = 0;
    __syncthreads();

    // ---- Phase A: bin triangles; candidates held in registers ----
    float cz[CPT];
    int   ct[CPT];
    int   nc = 0;
#pragma unroll
    for (int itr = 0; itr < CPT; itr++) {
        int t = tid + itr * NTHR;
        if (t >= K) break;
        float4 bb = g_bbox[t];
        if (bb.z < txLo || bb.x > txHi || bb.w < tyLo || bb.y > tyHi) continue;

        float4 v0 = g_v0[t];
        float4 v1 = g_v1[t];
        float ax = v0.x, ay = v0.y, bx = v0.z, by = v0.w;
        float cx = v1.x, cy = v1.y, w = v1.z;

        // per-edge eval at max corner (reject) and min corner (coverage)
        float eABmin, eCBmin, eCAmin;
        {
            float gx = (ay - by), gy = -(ax - bx);
            float exM = (gx > 0.f) ? txHi : txLo, eyM = (gy > 0.f) ? tyHi : tyLo;
            if (edgef(exM, eyM, bx, by, ax, ay) <= -1e-6f) continue;
            float exm = (gx > 0.f) ? txLo : txHi, eym = (gy > 0.f) ? tyLo : tyHi;
            eABmin = edgef(exm, eym, bx, by, ax, ay);
        }
        {
            float gx = (by - cy), gy = -(bx - cx);
            float exM = (gx > 0.f) ? txHi : txLo, eyM = (gy > 0.f) ? tyHi : tyLo;
            if (edgef(exM, eyM, cx, cy, bx, by) <= -1e-6f) continue;
            float exm = (gx > 0.f) ? txLo : txHi, eym = (gy > 0.f) ? tyLo : tyHi;
            eCBmin = edgef(exm, eym, cx, cy, bx, by);
        }
        {
            float gx = (cy - ay), gy = -(cx - ax);
            float exM = (gx > 0.f) ? txHi : txLo, eyM = (gy > 0.f) ? tyHi : tyLo;
            if (edgef(exM, eyM, ax, ay, cx, cy) <= -1e-6f) continue;
            float exm = (gx > 0.f) ? txLo : txHi, eym = (gy > 0.f) ? tyLo : tyHi;
            eCAmin = edgef(exm, eym, ax, ay, cx, cy);
        }

        // tile-max z upper bound from z-plane (guard folded into Zcg)
        float zb;
        float4 zp = g_zp[t];
        if (w < 1e-4f) {
            zb = FLT_MAX;
        } else {
            float mx = (zp.x > 0.f) ? txHi : txLo;
            float my = (zp.y > 0.f) ? tyHi : tyLo;
            zb = zp.x * mx + zp.y * my + zp.z;

            // coverage: exact inside at every tile pixel guaranteed when all
            // edge functions clear +1e-3 at their min corners
            if (eABmin > 1e-3f && eCBmin > 1e-3f && eCAmin > 1e-3f) {
                float mx2 = (zp.x > 0.f) ? txLo : txHi;
                float my2 = (zp.y > 0.f) ? tyLo : tyHi;
                float zlo = zp.x * mx2 + zp.y * my2 + (zp.z - 3.0f * zp.w);
                atomicMax(&s_floor_enc, fenc(zlo));
            }
        }
        cz[nc] = zb;
        ct[nc] = t;
        nc++;
    }
    __syncthreads();

    // ---- floor prune BEFORE sort (exact-safe) ----
    const unsigned int floor_enc = max(g_zinit_enc, s_floor_enc);
    {
        int m = 0;
#pragma unroll
        for (int k = 0; k < CPT; k++) {
            if (k >= nc) break;
            unsigned int e = fenc(cz[k]);
            if (e >= floor_enc) {
                cz[m] = cz[k];
                ct[m] = ct[k];
                m++;
                if (cz[k] < FLT_MAX) {
                    atomicMin(&s_encmin, e);
                    atomicMax(&s_encmax, e);
                }
            }
        }
        nc = m;
    }
    __syncthreads();

    // ---- counting sort over survivors (descending z-bound, NB buckets) ----
    float zmin, rangeInv, bw;
    {
        unsigned int emin = s_encmin, emax = s_encmax;
        float fzmin, fzmax;
        if (emin > emax) { fzmin = 0.f; fzmax = 1.f; }
        else { fzmin = fdec(emin); fzmax = fdec(emax); }
        if (!(fzmax > fzmin)) fzmax = fzmin + 1.0f;
        zmin = fzmin;
        bw = (fzmax - fzmin) / (float)NB;
        rangeInv = (float)NB / (fzmax - fzmin);
    }

    int cb[CPT];
#pragma unroll
    for (int k = 0; k < CPT; k++) {
        if (k >= nc) break;
        float zb = cz[k];
        int ib = (zb >= FLT_MAX) ? (NB - 1)
                                 : min(NB - 1, max(0, (int)((zb - zmin) * rangeInv)));
        cb[k] = ib;
        atomicAdd(&s_hist[NB - 1 - ib], 1);
    }
    __syncthreads();

    // exclusive prefix sum over NB=256 buckets (first 8 warps only)
    if (tid < NB) {
        int h = s_hist[tid];
        int v = h;
#pragma unroll
        for (int o = 1; o < 32; o <<= 1) {
            int u = __shfl_up_sync(0xffffffffu, v, o);
            if (lane >= o) v += u;
        }
        if (lane == 31) s_wsum[wid] = v;
        __syncthreads();
        if (tid == 0) {
            int acc = 0;
#pragma unroll
            for (int k = 0; k < 8; k++) { int t2 = s_wsum[k]; s_wsum[k] = acc; acc += t2; }
            s_total = acc;
        }
        __syncthreads();
        s_hist[tid] = v - h + s_wsum[wid];
    } else {
        __syncthreads();
        __syncthreads();
    }
    __syncthreads();
    const int n = min(s_total, MAXBIN);

    // scatter survivors in (approximately) descending-bound order
#pragma unroll
    for (int k = 0; k < CPT; k++) {
        if (k >= nc) break;
        int ib = cb[k];
        int t = ct[k];
        float keyz = (cz[k] >= FLT_MAX) ? FLT_MAX
                                        : zmin + (float)(ib + 2) * bw;  // ub + slack
        int pos = atomicAdd(&s_hist[NB - 1 - ib], 1);
        if (pos < MAXBIN) {
            float4 eab = g_eAB[t];
            float4 ecb = g_eCB[t];
            float4 zp  = g_zp[t];
            s_e0[pos] = eab;                                   // w in .w
            s_e1[pos] = make_float4(ecb.x, ecb.y, ecb.z,
                                    __uint_as_float((unsigned int)t));
            s_e2[pos] = make_float4(zp.x, zp.y, zp.z,
                                    __uint_as_float(fenc(keyz)));
        }
    }
    __syncthreads();

    // ---- Phase B: two pixels per thread (same column), shared loads ----
    unsigned int be0 = floor_enc, be1 = floor_enc;
    float bz0 = fdec(floor_enc), bz1 = bz0;
    int   bi0 = -1, bi1 = -1;
    float w1p0 = 0.f, w2p0 = 0.f, w1p1 = 0.f, w2p1 = 0.f;

    for (int k = 0; k < n; k++) {
        float4 e2 = s_e2[k];
        unsigned int key = __float_as_uint(e2.w);
        bool a0 = (key >= be0);
        bool a1 = (key >= be1);
        if (!a0 && !a1) break;                 // sorted-bound break (both done)

        // zub = Zx*px + Zy*py + Zcg; share the px term
        float zx = e2.x * px;
        float zub0 = zx + fmaf(e2.y, py0, e2.z);
        float zub1 = zx + fmaf(e2.y, py1, e2.z);
        bool c0 = a0 && (zub0 >= bz0);
        bool c1 = a1 && (zub1 >= bz1);
        if (!c0 && !c1) continue;

        float4 e0 = s_e0[k];
        float4 e1 = s_e1[k];
        float ax_ = e0.x * px, bx_ = e1.x * px;
        float pab0 = ax_ + fmaf(e0.y, py0, e0.z);
        float pcb0 = bx_ + fmaf(e1.y, py0, e1.z);
        float pca0 = (e0.w - pab0) - pcb0;
        float pab1 = ax_ + fmaf(e0.y, py1, e0.z);
        float pcb1 = bx_ + fmaf(e1.y, py1, e1.z);
        float pca1 = (e0.w - pab1) - pcb1;
        bool q0 = c0 && pab0 > -EPS_E && pcb0 > -EPS_E && pca0 > -EPS_E;
        bool q1 = c1 && pab1 > -EPS_E && pcb1 > -EPS_E && pca1 > -EPS_E;
        if (!q0 && !q1) continue;

        int t = (int)__float_as_uint(e1.w);
        float4 v0 = g_v0[t];
        float4 v1 = g_v1[t];
        float4 wz = g_wz[t];

        if (q0) {
            float pAB = edgef(px, py0, v0.z, v0.w, v0.x, v0.y);
            float pCB = edgef(px, py0, v1.x, v1.y, v0.z, v0.w);
            float pCA = edgef(px, py0, v0.x, v0.y, v1.x, v1.y);
            if (pAB > 0.f && pCB > 0.f && pCA > 0.f) {
                float w1 = __fdiv_rn(pCB, wz.x);
                float w2 = __fdiv_rn(pCA, wz.x);
                float w3 = __fsub_rn(__fsub_rn(1.0f, w1), w2);
                float z = __fadd_rn(__fadd_rn(__fmul_rn(w1, wz.y),
                                              __fmul_rn(w2, wz.z)),
                                    __fmul_rn(w3, wz.w));
                if (z > bz0 || (z == bz0 && t > bi0)) {
                    bz0 = z; be0 = fenc(z); bi0 = t; w1p0 = w1; w2p0 = w2;
                }
            }
        }
        if (q1) {
            float pAB = edgef(px, py1, v0.z, v0.w, v0.x, v0.y);
            float pCB = edgef(px, py1, v1.x, v1.y, v0.z, v0.w);
            float pCA = edgef(px, py1, v0.x, v0.y, v1.x, v1.y);
            if (pAB > 0.f && pCB > 0.f && pCA > 0.f) {
                float w1 = __fdiv_rn(pCB, wz.x);
                float w2 = __fdiv_rn(pCA, wz.x);
                float w3 = __fsub_rn(__fsub_rn(1.0f, w1), w2);
                float z = __fadd_rn(__fadd_rn(__fmul_rn(w1, wz.y),
                                              __fmul_rn(w2, wz.z)),
                                    __fmul_rn(w3, wz.w));
                if (z > bz1 || (z == bz1 && t > bi1)) {
                    bz1 = z; be1 = fenc(z); bi1 = t; w1p1 = w1; w2p1 = w2;
                }
            }
        }
    }

    if (jp < S) {
        if (i0p < S) shade_pixel(uvmap, out, bi0, w1p0, w2p0, i0p, jp, S, T);
        if (i1p < S) shade_pixel(uvmap, out, bi1, w1p1, w2p1, i1p, jp, S, T);
    }
}

// ---------------------------------------------------------------------------
extern "C" void kernel_launch(void* const* d_in, const int* in_sizes, int n_in,
                              void* d_out, int out_size) {
    const float* vertices = (const float*)d_in[0];
    const int*   faces    = (const int*)  d_in[1];
    const float* uv       = (const float*)d_in[2];
    const int*   uvfaces  = (const int*)  d_in[3];
    const float* uvmap    = (const float*)d_in[4];

    int V = in_sizes[0] / 3;
    int K = in_sizes[1] / 3;
    int T = (int)(sqrt((double)in_sizes[4] / 3.0) + 0.5);
    int S = (int)(sqrt((double)out_size / 4.0) + 0.5);
    int Keff = (K < MAXTRI) ? K : MAXTRI;

    void* zinit_addr = nullptr;
    cudaGetSymbolAddress(&zinit_addr, g_zinit_enc);
    cudaMemsetAsync(zinit_addr, 0xFF, sizeof(unsigned int), 0);

    int KV = (K > V) ? K : V;
    setup_kernel<<<(KV + 255) / 256, 256>>>(vertices, faces, uv, uvfaces,
                                            Keff, V);

    const int DYN = 3 * MAXBIN * sizeof(float4);   // 49152 bytes
    static int attr_done = 0;
    if (!attr_done) {
        cudaFuncSetAttribute(render_kernel,
                             cudaFuncAttributeMaxDynamicSharedMemorySize, DYN);
        attr_done = 1;
    }

    dim3 grid((S + TILE_W - 1) / TILE_W, (S + TILE_H - 1) / TILE_H);
    render_kernel<<<grid, NTHR, DYN>>>(uvmap, (float*)d_out, Keff, S, T);
}